// round 11
// baseline (speedup 1.0000x reference)
#include <cuda_runtime.h>
#include <cuda_fp16.h>
#include <cstdint>

#define NBLK   128
#define GRP    64
#define NTHR   128
#define TSTEPS 512
#define OUTN   (512*128*512)

// ---- smem byte offsets -----------------------------------------------------
#define SM_BIAS 0          // 32 f32
#define SM_ZSH  128        // 32*132*4 = 16896
#define SM_W    17024      // B frags: [64 sg][4 nt][32 lane]*8B = 65536
#define SM_A    82944      // 4 bufs * 16KB = 65536
#define SM_TOT  148480

// ---- persistent state ------------------------------------------------------
__device__ __align__(16) __half g_x[(size_t)TSTEPS*128*512];
__device__ __align__(16) __half g_hst[2][2][128*512];   // [layer][pingpong]
__device__ __align__(16) __half g_mid[2][128*512];      // [pingpong]
__device__ unsigned g_bar_count;
__device__ volatile unsigned g_bar_gen;
__device__ unsigned g_cntM, g_cntL1;
__device__ volatile unsigned g_genM, g_genL1;

// ---- reset kernel (graph-replay-safe absolute flags) -----------------------
__global__ void reset_flags() {
    g_bar_count = 0; g_bar_gen = 0;
    g_cntM = 0; g_cntL1 = 0; g_genM = 0; g_genL1 = 0;
}

// ---- full 128-CTA barrier (used once after init) ---------------------------
__device__ __forceinline__ void grid_barrier_full() {
    __syncthreads();
    if (threadIdx.x == 0) {
        __threadfence();
        unsigned gen = g_bar_gen;
        if (atomicAdd(&g_bar_count, 1u) == NBLK - 1) {
            g_bar_count = 0;
            __threadfence();
            g_bar_gen = gen + 1;
        } else {
            while (g_bar_gen == gen) { __nanosleep(20); }
        }
        __threadfence();
    }
    __syncthreads();
}

// ---- group barrier ops (tid0-only) -----------------------------------------
__device__ __forceinline__ void grp_arrive(unsigned* cnt, volatile unsigned* gen) {
    __threadfence();
    if (atomicAdd(cnt, 1u) == GRP - 1) {
        *cnt = 0;
        __threadfence();
        *gen = *gen + 1;
    }
}
__device__ __forceinline__ void grp_wait(volatile unsigned* gen, unsigned target) {
    while ((int)(*gen - target) < 0) { __nanosleep(20); }
    __threadfence();
}

// ---- asm helpers -----------------------------------------------------------
__device__ __forceinline__ void cp16(uint32_t s, const void* g) {
    asm volatile("cp.async.cg.shared.global [%0], [%1], 16;" :: "r"(s), "l"(g));
}
__device__ __forceinline__ void cp_commit() { asm volatile("cp.async.commit_group;"); }
template<int N> __device__ __forceinline__ void cp_wait() {
    asm volatile("cp.async.wait_group %0;" :: "n"(N));
}
__device__ __forceinline__ void ldm4(uint32_t (&a)[4], uint32_t addr) {
    asm volatile("ldmatrix.sync.aligned.m8n8.x4.shared.b16 {%0,%1,%2,%3}, [%4];"
                 : "=r"(a[0]), "=r"(a[1]), "=r"(a[2]), "=r"(a[3]) : "r"(addr));
}
__device__ __forceinline__ void mma(float (&d)[4], const uint32_t (&a)[4],
                                    uint32_t b0, uint32_t b1) {
    asm volatile("mma.sync.aligned.m16n8k16.row.col.f32.f16.f16.f32 "
        "{%0,%1,%2,%3}, {%4,%5,%6,%7}, {%8,%9}, {%0,%1,%2,%3};"
        : "+f"(d[0]), "+f"(d[1]), "+f"(d[2]), "+f"(d[3])
        : "r"(a[0]), "r"(a[1]), "r"(a[2]), "r"(a[3]), "r"(b0), "r"(b1));
}
__device__ __forceinline__ void stcg4v(void* p, uint32_t a, uint32_t b,
                                       uint32_t c, uint32_t d) {
    asm volatile("st.global.cg.v4.b32 [%0], {%1,%2,%3,%4};"
                 :: "l"(p), "r"(a), "r"(b), "r"(c), "r"(d));
}
__device__ __forceinline__ void stcg16(void* p, unsigned short v) {
    asm volatile("st.global.cg.u16 [%0], %1;" :: "l"(p), "h"(v));
}

__device__ __forceinline__ float sigm(float x) { return 1.0f / (1.0f + __expf(-x)); }

// ---- A staging: warp w stages its 32-row band of chunk c -------------------
__device__ __forceinline__ void stage32(const __half* src, int c,
                                        uint32_t abase, int w, int lane) {
    int coff = (c & 7) << 6;
    uint32_t dst = abase + (c & 3) * 16384;
    int rq = lane >> 3, cq = lane & 7;
#pragma unroll
    for (int jj = 0; jj < 8; ++jj) {
        int row = w * 32 + jj * 4 + rq;
        uint32_t d = dst + row * 128 + ((cq ^ (row & 7)) << 4);
        cp16(d, src + (size_t)row * 512 + coff + cq * 8);
    }
}

// ---- per-chunk GEMM: 4 ks x 4 nt x 2 mt = 32 HMMA (single product) ---------
__device__ __forceinline__ void chunk_mma(int c, uint32_t abase, const uint2* bf,
                                          int w, int lane, float (&acc)[2][4][4]) {
    int sub = lane >> 3, lrow = lane & 7;
    uint32_t ab = abase + (c & 3) * 16384;
#pragma unroll
    for (int ks = 0; ks < 4; ++ks) {
        uint32_t Ah[2][4];
#pragma unroll
        for (int mt = 0; mt < 2; ++mt) {
            int r = w * 32 + mt * 16 + ((sub & 1) << 3) + lrow;
            uint32_t aoff = r * 128 + (((2 * ks + (sub >> 1)) ^ (r & 7)) << 4);
            ldm4(Ah[mt], ab + aoff);
        }
        int sg = c * 4 + ks;
#pragma unroll
        for (int nt = 0; nt < 4; ++nt) {
            uint2 Bh = bf[(sg * 4 + nt) * 32 + lane];
#pragma unroll
            for (int mt = 0; mt < 2; ++mt)
                mma(acc[mt][nt], Ah[mt], Bh.x, Bh.y);
        }
    }
}

// ---- 8-chunk pipelined half ------------------------------------------------
__device__ __forceinline__ void run_half(const __half* src, int cbase,
                                         uint32_t abase, const uint2* bf,
                                         int w, int lane, float (&acc)[2][4][4]) {
#pragma unroll
    for (int c = 0; c < 4; ++c) { stage32(src, cbase + c, abase, w, lane); cp_commit(); }
#pragma unroll 1
    for (int i = 0; i < 8; ++i) {
        cp_wait<3>();
        chunk_mma(cbase + i, abase, bf, w, lane, acc);
        if (i < 4) stage32(src, cbase + i + 4, abase, w, lane);
        cp_commit();
    }
}

// ---- main persistent kernel ------------------------------------------------
__global__ void __launch_bounds__(NTHR, 1) lstm_tc(
    const float* __restrict__ hxs, const float* __restrict__ masks,
    const float* __restrict__ W_ih, const float* __restrict__ W_hh,
    const float* __restrict__ b_ih, const float* __restrict__ b_hh,
    float* __restrict__ out)
{
    extern __shared__ __align__(1024) char sm[];
    uint32_t smb = (uint32_t)__cvta_generic_to_shared(sm);
    int tid = threadIdx.x, blk = blockIdx.x, w = tid >> 5, lane = tid & 31;
    int isL0 = (blk < GRP);
    int g = isL0 ? blk : (blk - GRP);
    int l = isL0 ? 0 : 1;
    uint32_t abase = smb + SM_A;

    // ---- weight conversion: this CTA's 32 gate cols, K=1024, plain fp16 ----
    unsigned short* bw = (unsigned short*)(sm + SM_W);
    for (int idx = tid; idx < 32 * 1024; idx += NTHR) {
        int col = idx >> 10, k = idx & 1023;
        int grow = (col >> 3) * 512 + g * 8 + (col & 7);
        float wv = (k < 512)
            ? W_ih[((size_t)l * 2048 + grow) * 512 + k]
            : W_hh[((size_t)l * 2048 + grow) * 512 + (k - 512)];
        unsigned short hi = __half_as_ushort(__float2half_rn(wv));
        int sg = k >> 4, kk = k & 15;
        int reg = (kk >> 3) & 1, pos = kk & 1;
        int lamd = (col & 7) * 4 + ((kk & 7) >> 1);
        int nt = col >> 3;
        bw[(sg * 4 + nt) * 128 + lamd * 4 + reg * 2 + pos] = hi;
    }
    if (tid < 32) {
        int c = tid;
        int grow = (c >> 3) * 512 + g * 8 + (c & 7);
        ((float*)(sm + SM_BIAS))[c] = b_ih[l * 2048 + grow] + b_hh[l * 2048 + grow];
    }

    // ---- init masked h state (pp=0): grid-strided over both layers ---------
    for (int idx = blk * NTHR + tid; idx < 2 * 65536; idx += NBLK * NTHR) {
        int ll = idx >> 16, r = idx & 65535;
        int n = r >> 9, jj = r & 511;
        float v = hxs[(size_t)ll * 131072 + n * 1024 + jj] * __ldg(masks + n);
        stcg16(&g_hst[ll][0][r], __half_as_ushort(__float2half_rn(v)));
    }
    // c-state: thread n = tid owns 8 units of this CTA's layer
    float creg[8];
#pragma unroll
    for (int u = 0; u < 8; ++u)
        creg[u] = hxs[(size_t)l * 131072 + tid * 1024 + 512 + g * 8 + u];

    grid_barrier_full();
    const uint2* bf = (const uint2*)(sm + SM_W);
    float* zsh = (float*)(sm + SM_ZSH);
    const float* bs = (const float*)(sm + SM_BIAS);

#pragma unroll 1
    for (int t = 0; t < TSTEPS; ++t) {
        int pr = t & 1, pw = pr ^ 1, mb = t & 1;
        float acc[2][4][4] = {};

        if (isL0) {
            // half A: x_t chunks 0-7 (no dependency)
            run_half(g_x + (size_t)t * 65536, 0, abase, bf, w, lane, acc);
            // wait: own group's h0(t-1) done; L1 freed mid(t) buffer
            if (tid == 0) {
                grp_wait(&g_genM, (unsigned)t);
                if (t >= 2) grp_wait(&g_genL1, (unsigned)(t - 1));
            }
            __syncthreads();
            // half B: recurrent h0(t-1) chunks 8-15
            run_half(g_hst[0][pr], 8, abase, bf, w, lane, acc);
        } else {
            // wait: own group's h1(t-1) done
            if (tid == 0) grp_wait(&g_genL1, (unsigned)t);
            __syncthreads();
            // half A: recurrent h1(t-1) chunks 8-15
            run_half(g_hst[1][pr], 8, abase, bf, w, lane, acc);
            // wait: mid(t) ready (all 64 L0 CTAs finished step t)
            if (tid == 0) grp_wait(&g_genM, (unsigned)(t + 1));
            __syncthreads();
            // half B: mid chunks 0-7
            run_half(g_mid[mb], 0, abase, bf, w, lane, acc);
        }

        // ---- epilogue: z transpose -> gates -> state writes -----------------
#pragma unroll
        for (int mt = 0; mt < 2; ++mt)
#pragma unroll
            for (int nt = 0; nt < 4; ++nt) {
                int m0 = w * 32 + mt * 16 + (lane >> 2);
                int n0 = nt * 8 + (lane & 3) * 2;
                zsh[n0 * 132 + m0]           = acc[mt][nt][0];
                zsh[(n0 + 1) * 132 + m0]     = acc[mt][nt][1];
                zsh[n0 * 132 + m0 + 8]       = acc[mt][nt][2];
                zsh[(n0 + 1) * 132 + m0 + 8] = acc[mt][nt][3];
            }
        __syncthreads();

        int n = tid;
        float m  = __ldg(masks + t * 128 + n);
        float mn = (t < TSTEPS - 1) ? __ldg(masks + (t + 1) * 128 + n) : 0.f;
        unsigned short sh[8], th[8];
        float hv[8];
#pragma unroll
        for (int u = 0; u < 8; ++u) {
            float zi = zsh[(0  + u) * 132 + n] + bs[u];
            float zf = zsh[(8  + u) * 132 + n] + bs[8 + u];
            float zg = zsh[(16 + u) * 132 + n] + bs[16 + u];
            float zo = zsh[(24 + u) * 132 + n] + bs[24 + u];
            float ii = sigm(zi), ff = sigm(zf), oo = sigm(zo);
            float gg = tanhf(zg);
            float cc = ff * (creg[u] * m) + ii * gg;
            float hh = oo * tanhf(cc);
            creg[u] = cc;
            hv[u] = hh;
            sh[u] = __half_as_ushort(__float2half_rn(hh * mn));
            if (isL0) th[u] = __half_as_ushort(__float2half_rn(hh));
        }
        size_t base = (size_t)n * 512 + g * 8;
        stcg4v(&g_hst[l][pw][base],
               sh[0] | ((uint32_t)sh[1] << 16), sh[2] | ((uint32_t)sh[3] << 16),
               sh[4] | ((uint32_t)sh[5] << 16), sh[6] | ((uint32_t)sh[7] << 16));
        if (isL0) {
            stcg4v(&g_mid[mb][base],
                   th[0] | ((uint32_t)th[1] << 16), th[2] | ((uint32_t)th[3] << 16),
                   th[4] | ((uint32_t)th[5] << 16), th[6] | ((uint32_t)th[7] << 16));
        } else {
            float* op = out + (size_t)t * 65536 + base;
            *(float4*)op       = make_float4(hv[0], hv[1], hv[2], hv[3]);
            *(float4*)(op + 4) = make_float4(hv[4], hv[5], hv[6], hv[7]);
        }
        if (t == TSTEPS - 1) {
#pragma unroll
            for (int u = 0; u < 8; ++u) {
                out[OUTN + l * 131072 + n * 1024 + g * 8 + u]       = hv[u];
                out[OUTN + l * 131072 + n * 1024 + 512 + g * 8 + u] = creg[u];
            }
        }
        __syncthreads();   // zsh reusable; all state writes issued

        if (tid == 0) {
            if (isL0) grp_arrive(&g_cntM, &g_genM);
            else      grp_arrive(&g_cntL1, &g_genL1);
        }
    }
}

// ---- x -> fp16 -------------------------------------------------------------
__global__ void __launch_bounds__(256) xconv(const float* __restrict__ x) {
    size_t i = (size_t)blockIdx.x * 256 + threadIdx.x;
    if (i >= (size_t)OUTN / 4) return;
    float4 v = __ldg(((const float4*)x) + i);
    unsigned short h0 = __half_as_ushort(__float2half_rn(v.x));
    unsigned short h1 = __half_as_ushort(__float2half_rn(v.y));
    unsigned short h2 = __half_as_ushort(__float2half_rn(v.z));
    unsigned short h3 = __half_as_ushort(__float2half_rn(v.w));
    *(uint2*)(g_x + i * 4) = make_uint2(h0 | ((uint32_t)h1 << 16),
                                        h2 | ((uint32_t)h3 << 16));
}

// ---- LayerNorm -------------------------------------------------------------
__global__ void __launch_bounds__(256) ln_kernel(float* __restrict__ out,
                                                 const float* __restrict__ gamma,
                                                 const float* __restrict__ beta)
{
    int lane = threadIdx.x & 31;
    int row  = blockIdx.x * 8 + (threadIdx.x >> 5);
    float* p = out + (size_t)row * 512;
    float4 v[4];
    float s = 0.f, sq = 0.f;
#pragma unroll
    for (int k = 0; k < 4; ++k) {
        v[k] = ((const float4*)p)[(k << 5) + lane];
        s += v[k].x + v[k].y + v[k].z + v[k].w;
        sq = fmaf(v[k].x, v[k].x, sq); sq = fmaf(v[k].y, v[k].y, sq);
        sq = fmaf(v[k].z, v[k].z, sq); sq = fmaf(v[k].w, v[k].w, sq);
    }
#pragma unroll
    for (int o = 16; o; o >>= 1) {
        s  += __shfl_xor_sync(0xffffffffu, s,  o);
        sq += __shfl_xor_sync(0xffffffffu, sq, o);
    }
    float mean = s * (1.0f / 512.0f);
    float inv  = rsqrtf(sq * (1.0f / 512.0f) - mean * mean + 1e-5f);
#pragma unroll
    for (int k = 0; k < 4; ++k) {
        float4 gm = ((const float4*)gamma)[(k << 5) + lane];
        float4 bt = ((const float4*)beta)[(k << 5) + lane];
        float4 r;
        r.x = (v[k].x - mean) * inv * gm.x + bt.x;
        r.y = (v[k].y - mean) * inv * gm.y + bt.y;
        r.z = (v[k].z - mean) * inv * gm.z + bt.z;
        r.w = (v[k].w - mean) * inv * gm.w + bt.w;
        ((float4*)p)[(k << 5) + lane] = r;
    }
}

// ---------------------------------------------------------------------------
extern "C" void kernel_launch(void* const* d_in, const int* in_sizes, int n_in,
                              void* d_out, int out_size) {
    const float* x     = (const float*)d_in[0];
    const float* hxs   = (const float*)d_in[1];
    const float* masks = (const float*)d_in[2];
    const float* W_ih  = (const float*)d_in[3];
    const float* W_hh  = (const float*)d_in[4];
    const float* b_ih  = (const float*)d_in[5];
    const float* b_hh  = (const float*)d_in[6];
    const float* gamma = (const float*)d_in[7];
    const float* beta  = (const float*)d_in[8];
    float* out = (float*)d_out;

    cudaFuncSetAttribute(lstm_tc, cudaFuncAttributeMaxDynamicSharedMemorySize, SM_TOT);

    reset_flags<<<1, 1>>>();
    xconv<<<(OUTN / 4 + 255) / 256, 256>>>(x);
    lstm_tc<<<NBLK, NTHR, SM_TOT>>>(hxs, masks, W_ih, W_hh, b_ih, b_hh, out);
    ln_kernel<<<65536 / 8, 256>>>(out, gamma, beta);
}

// round 13
// speedup vs baseline: 1.7243x; 1.7243x over previous
#include <cuda_runtime.h>
#include <cuda_fp16.h>
#include <cstdint>

#define NBLK   128
#define GRP    64
#define NTHR   128
#define TSTEPS 512
#define OUTN   (512*128*512)

// ---- smem byte offsets -----------------------------------------------------
#define SM_BIAS 0          // 32 f32
#define SM_ZSH  128        // 32*132*4 = 16896
#define SM_W    17024      // B frags: [64 sg][4 nt][32 lane]*8B = 65536
#define SM_A    82944      // 8 bufs * 16KB = 131072
#define SM_TOT  214016

// ---- persistent state ------------------------------------------------------
__device__ __align__(16) __half g_x[(size_t)TSTEPS*128*512];
__device__ __align__(16) __half g_hst[2][2][128*512];   // [layer][pingpong]
__device__ __align__(16) __half g_mid[2][128*512];      // [pingpong]
__device__ unsigned g_bar_count;
__device__ volatile unsigned g_bar_gen;
__device__ __align__(256) unsigned g_flagM[GRP];    // L0 CTA g done step t => t+1
__device__ __align__(256) unsigned g_flagL1[GRP];   // L1 CTA g done step t => t+1

// ---- reset kernel (graph-replay-safe) --------------------------------------
__global__ void reset_flags() {
    g_bar_count = 0; g_bar_gen = 0;
    for (int i = 0; i < GRP; ++i) { g_flagM[i] = 0; g_flagL1[i] = 0; }
}

// ---- full 128-CTA barrier (once, after init) -------------------------------
__device__ __forceinline__ void grid_barrier_full() {
    __syncthreads();
    if (threadIdx.x == 0) {
        __threadfence();
        unsigned gen = g_bar_gen;
        if (atomicAdd(&g_bar_count, 1u) == NBLK - 1) {
            g_bar_count = 0;
            __threadfence();
            g_bar_gen = gen + 1;
        } else {
            while (g_bar_gen == gen) { __nanosleep(20); }
        }
        __threadfence();
    }
    __syncthreads();
}

// ---- distributed flag barrier ----------------------------------------------
__device__ __forceinline__ unsigned ld_acq(const unsigned* p) {
    unsigned v;
    asm volatile("ld.acquire.gpu.b32 %0, [%1];" : "=r"(v) : "l"(p) : "memory");
    return v;
}
__device__ __forceinline__ void st_rel(unsigned* p, unsigned v) {
    asm volatile("st.release.gpu.b32 [%0], %1;" :: "l"(p), "r"(v) : "memory");
}
// all threads call; 64 threads poll 64 slots in parallel, then block-sync
__device__ __forceinline__ void wait_flags(unsigned* flags, int target) {
    if (target > 0 && (int)threadIdx.x < GRP) {
        while ((int)ld_acq(flags + threadIdx.x) < target) { __nanosleep(20); }
    }
    __syncthreads();
}

// ---- asm helpers -----------------------------------------------------------
__device__ __forceinline__ void cp16(uint32_t s, const void* g) {
    asm volatile("cp.async.cg.shared.global [%0], [%1], 16;" :: "r"(s), "l"(g));
}
__device__ __forceinline__ void cp_commit() { asm volatile("cp.async.commit_group;"); }
template<int N> __device__ __forceinline__ void cp_wait() {
    asm volatile("cp.async.wait_group %0;" :: "n"(N));
}
__device__ __forceinline__ void ldm4(uint32_t (&a)[4], uint32_t addr) {
    asm volatile("ldmatrix.sync.aligned.m8n8.x4.shared.b16 {%0,%1,%2,%3}, [%4];"
                 : "=r"(a[0]), "=r"(a[1]), "=r"(a[2]), "=r"(a[3]) : "r"(addr));
}
__device__ __forceinline__ void mma(float (&d)[4], const uint32_t (&a)[4],
                                    uint32_t b0, uint32_t b1) {
    asm volatile("mma.sync.aligned.m16n8k16.row.col.f32.f16.f16.f32 "
        "{%0,%1,%2,%3}, {%4,%5,%6,%7}, {%8,%9}, {%0,%1,%2,%3};"
        : "+f"(d[0]), "+f"(d[1]), "+f"(d[2]), "+f"(d[3])
        : "r"(a[0]), "r"(a[1]), "r"(a[2]), "r"(a[3]), "r"(b0), "r"(b1));
}
__device__ __forceinline__ void stcg4v(void* p, uint32_t a, uint32_t b,
                                       uint32_t c, uint32_t d) {
    asm volatile("st.global.cg.v4.b32 [%0], {%1,%2,%3,%4};"
                 :: "l"(p), "r"(a), "r"(b), "r"(c), "r"(d));
}
__device__ __forceinline__ void stcg16(void* p, unsigned short v) {
    asm volatile("st.global.cg.u16 [%0], %1;" :: "l"(p), "h"(v));
}

__device__ __forceinline__ float sigm(float x) { return 1.0f / (1.0f + __expf(-x)); }

// ---- A staging: warp w stages its 32-row band of k-chunk kc into buf -------
__device__ __forceinline__ void stage32(const __half* src, int kc, int buf,
                                        uint32_t abase, int w, int lane) {
    int coff = (kc & 7) << 6;
    uint32_t dst = abase + buf * 16384;
    int rq = lane >> 3, cq = lane & 7;
#pragma unroll
    for (int jj = 0; jj < 8; ++jj) {
        int row = w * 32 + jj * 4 + rq;
        uint32_t d = dst + row * 128 + ((cq ^ (row & 7)) << 4);
        cp16(d, src + (size_t)row * 512 + coff + cq * 8);
    }
}

// ---- per-chunk GEMM: 4 ks x 4 nt x 2 mt = 32 HMMA (single product) ---------
__device__ __forceinline__ void chunk_mma(int kc, int buf, uint32_t abase,
                                          const uint2* bf, int w, int lane,
                                          float (&acc)[2][4][4]) {
    int sub = lane >> 3, lrow = lane & 7;
    uint32_t ab = abase + buf * 16384;
#pragma unroll
    for (int ks = 0; ks < 4; ++ks) {
        uint32_t Ah[2][4];
#pragma unroll
        for (int mt = 0; mt < 2; ++mt) {
            int r = w * 32 + mt * 16 + ((sub & 1) << 3) + lrow;
            uint32_t aoff = r * 128 + (((2 * ks + (sub >> 1)) ^ (r & 7)) << 4);
            ldm4(Ah[mt], ab + aoff);
        }
        int sg = kc * 4 + ks;
#pragma unroll
        for (int nt = 0; nt < 4; ++nt) {
            uint2 Bh = bf[(sg * 4 + nt) * 32 + lane];
#pragma unroll
            for (int mt = 0; mt < 2; ++mt)
                mma(acc[mt][nt], Ah[mt], Bh.x, Bh.y);
        }
    }
}

// ---- whole-half: stage all 8 chunks upfront, then compute -------------------
template<int CB>
__device__ __forceinline__ void half8(const __half* src, uint32_t abase,
                                      const uint2* bf, int w, int lane,
                                      float (&acc)[2][4][4]) {
#pragma unroll
    for (int i = 0; i < 8; ++i) { stage32(src, CB + i, i, abase, w, lane); cp_commit(); }
    cp_wait<7>(); chunk_mma(CB + 0, 0, abase, bf, w, lane, acc);
    cp_wait<6>(); chunk_mma(CB + 1, 1, abase, bf, w, lane, acc);
    cp_wait<5>(); chunk_mma(CB + 2, 2, abase, bf, w, lane, acc);
    cp_wait<4>(); chunk_mma(CB + 3, 3, abase, bf, w, lane, acc);
    cp_wait<3>(); chunk_mma(CB + 4, 4, abase, bf, w, lane, acc);
    cp_wait<2>(); chunk_mma(CB + 5, 5, abase, bf, w, lane, acc);
    cp_wait<1>(); chunk_mma(CB + 6, 6, abase, bf, w, lane, acc);
    cp_wait<0>(); chunk_mma(CB + 7, 7, abase, bf, w, lane, acc);
}

// ---- main persistent kernel ------------------------------------------------
__global__ void __launch_bounds__(NTHR, 1) lstm_tc(
    const float* __restrict__ hxs, const float* __restrict__ masks,
    const float* __restrict__ W_ih, const float* __restrict__ W_hh,
    const float* __restrict__ b_ih, const float* __restrict__ b_hh,
    float* __restrict__ out)
{
    extern __shared__ __align__(1024) char sm[];
    uint32_t smb = (uint32_t)__cvta_generic_to_shared(sm);
    int tid = threadIdx.x, blk = blockIdx.x, w = tid >> 5, lane = tid & 31;
    int isL0 = (blk < GRP);
    int g = isL0 ? blk : (blk - GRP);
    int l = isL0 ? 0 : 1;
    uint32_t abase = smb + SM_A;

    // ---- weight conversion: this CTA's 32 gate cols, K=1024, plain fp16 ----
    unsigned short* bw = (unsigned short*)(sm + SM_W);
    for (int idx = tid; idx < 32 * 1024; idx += NTHR) {
        int col = idx >> 10, k = idx & 1023;
        int grow = (col >> 3) * 512 + g * 8 + (col & 7);
        float wv = (k < 512)
            ? W_ih[((size_t)l * 2048 + grow) * 512 + k]
            : W_hh[((size_t)l * 2048 + grow) * 512 + (k - 512)];
        unsigned short hi = __half_as_ushort(__float2half_rn(wv));
        int sg = k >> 4, kk = k & 15;
        int reg = (kk >> 3) & 1, pos = kk & 1;
        int lamd = (col & 7) * 4 + ((kk & 7) >> 1);
        int nt = col >> 3;
        bw[(sg * 4 + nt) * 128 + lamd * 4 + reg * 2 + pos] = hi;
    }
    if (tid < 32) {
        int c = tid;
        int grow = (c >> 3) * 512 + g * 8 + (c & 7);
        ((float*)(sm + SM_BIAS))[c] = b_ih[l * 2048 + grow] + b_hh[l * 2048 + grow];
    }

    // ---- init masked h state (pp=0): grid-strided over both layers ---------
    for (int idx = blk * NTHR + tid; idx < 2 * 65536; idx += NBLK * NTHR) {
        int ll = idx >> 16, r = idx & 65535;
        int n = r >> 9, jj = r & 511;
        float v = hxs[(size_t)ll * 131072 + n * 1024 + jj] * __ldg(masks + n);
        stcg16(&g_hst[ll][0][r], __half_as_ushort(__float2half_rn(v)));
    }
    // c-state: thread n = tid owns 8 units of this CTA's layer
    float creg[8];
#pragma unroll
    for (int u = 0; u < 8; ++u)
        creg[u] = hxs[(size_t)l * 131072 + tid * 1024 + 512 + g * 8 + u];

    grid_barrier_full();
    const uint2* bf = (const uint2*)(sm + SM_W);
    float* zsh = (float*)(sm + SM_ZSH);
    const float* bs = (const float*)(sm + SM_BIAS);

#pragma unroll 1
    for (int t = 0; t < TSTEPS; ++t) {
        int pr = t & 1, pw = pr ^ 1, mb = t & 1;
        float acc[2][4][4] = {};

        if (isL0) {
            // half A: x_t (no dependency)
            half8<0>(g_x + (size_t)t * 65536, abase, bf, w, lane, acc);
            // wait: all L0 done step t-1 (h0 ready); L1 freed mid(t) buffer
            wait_flags(g_flagM, t);
            wait_flags(g_flagL1, t - 1);
            // half B: recurrent h0(t-1)
            half8<8>(g_hst[0][pr], abase, bf, w, lane, acc);
        } else {
            // wait: all L1 done step t-1 (h1 ready)
            wait_flags(g_flagL1, t);
            // half A: recurrent h1(t-1)
            half8<8>(g_hst[1][pr], abase, bf, w, lane, acc);
            // wait: mid(t) ready (all L0 done step t)
            wait_flags(g_flagM, t + 1);
            // half B: mid
            half8<0>(g_mid[mb], abase, bf, w, lane, acc);
        }

        // ---- epilogue: z transpose -> gates -> state writes -----------------
#pragma unroll
        for (int mt = 0; mt < 2; ++mt)
#pragma unroll
            for (int nt = 0; nt < 4; ++nt) {
                int m0 = w * 32 + mt * 16 + (lane >> 2);
                int n0 = nt * 8 + (lane & 3) * 2;
                zsh[n0 * 132 + m0]           = acc[mt][nt][0];
                zsh[(n0 + 1) * 132 + m0]     = acc[mt][nt][1];
                zsh[n0 * 132 + m0 + 8]       = acc[mt][nt][2];
                zsh[(n0 + 1) * 132 + m0 + 8] = acc[mt][nt][3];
            }
        __syncthreads();

        int n = tid;
        float m  = __ldg(masks + t * 128 + n);
        float mn = (t < TSTEPS - 1) ? __ldg(masks + (t + 1) * 128 + n) : 0.f;
        unsigned short sh[8], th[8];
        float hv[8];
#pragma unroll
        for (int u = 0; u < 8; ++u) {
            float zi = zsh[(0  + u) * 132 + n] + bs[u];
            float zf = zsh[(8  + u) * 132 + n] + bs[8 + u];
            float zg = zsh[(16 + u) * 132 + n] + bs[16 + u];
            float zo = zsh[(24 + u) * 132 + n] + bs[24 + u];
            float ii = sigm(zi), ff = sigm(zf), oo = sigm(zo);
            float gg = tanhf(zg);
            float cc = ff * (creg[u] * m) + ii * gg;
            float hh = oo * tanhf(cc);
            creg[u] = cc;
            hv[u] = hh;
            sh[u] = __half_as_ushort(__float2half_rn(hh * mn));
            if (isL0) th[u] = __half_as_ushort(__float2half_rn(hh));
        }
        size_t base = (size_t)n * 512 + g * 8;
        stcg4v(&g_hst[l][pw][base],
               sh[0] | ((uint32_t)sh[1] << 16), sh[2] | ((uint32_t)sh[3] << 16),
               sh[4] | ((uint32_t)sh[5] << 16), sh[6] | ((uint32_t)sh[7] << 16));
        if (isL0) {
            stcg4v(&g_mid[mb][base],
                   th[0] | ((uint32_t)th[1] << 16), th[2] | ((uint32_t)th[3] << 16),
                   th[4] | ((uint32_t)th[5] << 16), th[6] | ((uint32_t)th[7] << 16));
        } else {
            float* op = out + (size_t)t * 65536 + base;
            *(float4*)op       = make_float4(hv[0], hv[1], hv[2], hv[3]);
            *(float4*)(op + 4) = make_float4(hv[4], hv[5], hv[6], hv[7]);
        }
        if (t == TSTEPS - 1) {
#pragma unroll
            for (int u = 0; u < 8; ++u) {
                out[OUTN + l * 131072 + n * 1024 + g * 8 + u]       = hv[u];
                out[OUTN + l * 131072 + n * 1024 + 512 + g * 8 + u] = creg[u];
            }
        }
        __syncthreads();   // zsh reusable; all state writes issued

        if (tid == 0) {
            __threadfence();
            if (isL0) st_rel(&g_flagM[g],  (unsigned)(t + 1));
            else      st_rel(&g_flagL1[g], (unsigned)(t + 1));
        }
    }
}

// ---- x -> fp16 -------------------------------------------------------------
__global__ void __launch_bounds__(256) xconv(const float* __restrict__ x) {
    size_t i = (size_t)blockIdx.x * 256 + threadIdx.x;
    if (i >= (size_t)OUTN / 4) return;
    float4 v = __ldg(((const float4*)x) + i);
    unsigned short h0 = __half_as_ushort(__float2half_rn(v.x));
    unsigned short h1 = __half_as_ushort(__float2half_rn(v.y));
    unsigned short h2 = __half_as_ushort(__float2half_rn(v.z));
    unsigned short h3 = __half_as_ushort(__float2half_rn(v.w));
    *(uint2*)(g_x + i * 4) = make_uint2(h0 | ((uint32_t)h1 << 16),
                                        h2 | ((uint32_t)h3 << 16));
}

// ---- LayerNorm -------------------------------------------------------------
__global__ void __launch_bounds__(256) ln_kernel(float* __restrict__ out,
                                                 const float* __restrict__ gamma,
                                                 const float* __restrict__ beta)
{
    int lane = threadIdx.x & 31;
    int row  = blockIdx.x * 8 + (threadIdx.x >> 5);
    float* p = out + (size_t)row * 512;
    float4 v[4];
    float s = 0.f, sq = 0.f;
#pragma unroll
    for (int k = 0; k < 4; ++k) {
        v[k] = ((const float4*)p)[(k << 5) + lane];
        s += v[k].x + v[k].y + v[k].z + v[k].w;
        sq = fmaf(v[k].x, v[k].x, sq); sq = fmaf(v[k].y, v[k].y, sq);
        sq = fmaf(v[k].z, v[k].z, sq); sq = fmaf(v[k].w, v[k].w, sq);
    }
#pragma unroll
    for (int o = 16; o; o >>= 1) {
        s  += __shfl_xor_sync(0xffffffffu, s,  o);
        sq += __shfl_xor_sync(0xffffffffu, sq, o);
    }
    float mean = s * (1.0f / 512.0f);
    float inv  = rsqrtf(sq * (1.0f / 512.0f) - mean * mean + 1e-5f);
#pragma unroll
    for (int k = 0; k < 4; ++k) {
        float4 gm = ((const float4*)gamma)[(k << 5) + lane];
        float4 bt = ((const float4*)beta)[(k << 5) + lane];
        float4 r;
        r.x = (v[k].x - mean) * inv * gm.x + bt.x;
        r.y = (v[k].y - mean) * inv * gm.y + bt.y;
        r.z = (v[k].z - mean) * inv * gm.z + bt.z;
        r.w = (v[k].w - mean) * inv * gm.w + bt.w;
        ((float4*)p)[(k << 5) + lane] = r;
    }
}

// ---------------------------------------------------------------------------
extern "C" void kernel_launch(void* const* d_in, const int* in_sizes, int n_in,
                              void* d_out, int out_size) {
    const float* x     = (const float*)d_in[0];
    const float* hxs   = (const float*)d_in[1];
    const float* masks = (const float*)d_in[2];
    const float* W_ih  = (const float*)d_in[3];
    const float* W_hh  = (const float*)d_in[4];
    const float* b_ih  = (const float*)d_in[5];
    const float* b_hh  = (const float*)d_in[6];
    const float* gamma = (const float*)d_in[7];
    const float* beta  = (const float*)d_in[8];
    float* out = (float*)d_out;

    cudaFuncSetAttribute(lstm_tc, cudaFuncAttributeMaxDynamicSharedMemorySize, SM_TOT);

    reset_flags<<<1, 1>>>();
    xconv<<<(OUTN / 4 + 255) / 256, 256>>>(x);
    lstm_tc<<<NBLK, NTHR, SM_TOT>>>(hxs, masks, W_ih, W_hh, b_ih, b_hh, out);
    ln_kernel<<<65536 / 8, 256>>>(out, gamma, beta);
}